// round 15
// baseline (speedup 1.0000x reference)
#include <cuda_runtime.h>

// ============================================================================
// MultiHeadAttentionQuantum — algebraic form, fused, T-load amortized.
// ev_i = Σ_{a,b} T_i[a][b] m01[a] m23[b]  (81-term multilinear basis in
// {1,cos x_q,sin x_q}).  out = W ev + b.
// Fused kernel: 4 tokens/thread (2 f32x2 pairs). T rows (LDS.128, dup'd) are
// shared across both pairs via dual accumulation — halves the dominant LDS
// stream (L1 pipe was 64.5% busy vs fma 22.5%). Pair0 is projected inline
// into 32 packed register accumulators; pair1's ev is staged in smem (same
// thread, no sync) and projected in a second pass reusing the accumulators.
// ============================================================================

#define NQ      4
#define DIM     16
#define NH      8
#define NLAYERS 2
#define EMB     32
#define NTOK    (32 * 4096)
#define NBASIS  81
#define NROWS   (NH * 4 * 9)          // 288 T-rows (h, i, a)
#define ROWW    5                      // ulonglong2 slots per row (9 vals + pad)
#define BLK     64

typedef unsigned long long ull;

// ---- packed f32x2 helpers (Blackwell sm_103a) ------------------------------
__device__ __forceinline__ ull pk(float lo, float hi) {
    ull r; asm("mov.b64 %0, {%1, %2};" : "=l"(r) : "f"(lo), "f"(hi)); return r;
}
__device__ __forceinline__ void upk(ull v, float& lo, float& hi) {
    asm("mov.b64 {%0, %1}, %2;" : "=f"(lo), "=f"(hi) : "l"(v));
}
__device__ __forceinline__ ull f2mul(ull a, ull b) {
    ull d; asm("mul.rn.f32x2 %0, %1, %2;" : "=l"(d) : "l"(a), "l"(b)); return d;
}
__device__ __forceinline__ ull f2fma(ull a, ull b, ull c) {
    ull d; asm("fma.rn.f32x2 %0, %1, %2, %3;" : "=l"(d) : "l"(a), "l"(b), "l"(c)); return d;
}

// ---- global scratch (static device arrays; no allocation) ------------------
__device__ ulonglong2 g_T2[NROWS * ROWW];      // padded, dup'd T rows

// ============================================================================
// Gate helpers with COMPILE-TIME masks (static register indexing).
// ============================================================================
template<int M>
__device__ __forceinline__ void rot3(float* cr, float* ci, const float* p) {
    float c, s;
    __sincosf(0.5f * p[0], &s, &c);          // RX
#pragma unroll
    for (int j = 0; j < DIM; ++j) if (!(j & M)) {
        const int j1 = j | M;
        float a0r = cr[j],  a0i = ci[j];
        float a1r = cr[j1], a1i = ci[j1];
        cr[j]  = c * a0r + s * a1i;   ci[j]  = c * a0i - s * a1r;
        cr[j1] = c * a1r + s * a0i;   ci[j1] = c * a1i - s * a0r;
    }
    __sincosf(0.5f * p[1], &s, &c);          // RY
#pragma unroll
    for (int j = 0; j < DIM; ++j) if (!(j & M)) {
        const int j1 = j | M;
        float a0r = cr[j],  a0i = ci[j];
        float a1r = cr[j1], a1i = ci[j1];
        cr[j]  = c * a0r - s * a1r;   ci[j]  = c * a0i - s * a1i;
        cr[j1] = s * a0r + c * a1r;   ci[j1] = s * a0i + c * a1i;
    }
    __sincosf(0.5f * p[2], &s, &c);          // RZ
#pragma unroll
    for (int j = 0; j < DIM; ++j) if (!(j & M)) {
        const int j1 = j | M;
        float a0r = cr[j],  a0i = ci[j];
        float a1r = cr[j1], a1i = ci[j1];
        cr[j]  = c * a0r + s * a0i;   ci[j]  = c * a0i - s * a0r;
        cr[j1] = c * a1r - s * a1i;   ci[j1] = c * a1i + s * a1r;
    }
}

template<int CM, int TM>
__device__ __forceinline__ void cnot_g(float* cr, float* ci) {
#pragma unroll
    for (int j = 0; j < DIM; ++j) if ((j & CM) && !(j & TM)) {
        const int j1 = j | TM;
        float tr = cr[j]; cr[j] = cr[j1]; cr[j1] = tr;
        float ti = ci[j]; ci[j] = ci[j1]; ci[j1] = ti;
    }
}

// ============================================================================
// Kernel 1: per head, build U -> B_i -> T via SEPARABLE qubit sweeps.
// One block per head (8 blocks x 128 threads), params staged via smem.
// ============================================================================
__global__ void precompute_T_kernel(const float* __restrict__ params) {
    __shared__ float sPar[NLAYERS * NQ * 3];
    __shared__ float sUr[DIM * DIM], sUi[DIM * DIM];
    __shared__ float sA[4 * 256];    // ping
    __shared__ float sC[4 * 192];    // pong (max intermediate = 768)
    const int h   = blockIdx.x;
    const int tid = threadIdx.x;

    if (tid < NLAYERS * NQ * 3) sPar[tid] = params[h * NLAYERS * NQ * 3 + tid];
    __syncthreads();

    // ---- stage 1: threads 0..15 each evolve one COLUMN of U ----
    if (tid < DIM) {
        float cr[DIM], ci[DIM];
#pragma unroll
        for (int j = 0; j < DIM; ++j) { cr[j] = (j == tid) ? 1.0f : 0.0f; ci[j] = 0.0f; }
#pragma unroll
        for (int l = 0; l < NLAYERS; ++l) {
            const float* pb = sPar + l * NQ * 3;
            rot3<8>(cr, ci, pb + 0);
            rot3<4>(cr, ci, pb + 3);
            rot3<2>(cr, ci, pb + 6);
            rot3<1>(cr, ci, pb + 9);
            cnot_g<8, 4>(cr, ci);
            cnot_g<4, 2>(cr, ci);
            cnot_g<2, 1>(cr, ci);
            cnot_g<1, 8>(cr, ci);
        }
#pragma unroll
        for (int j = 0; j < DIM; ++j) { sUr[j * DIM + tid] = cr[j]; sUi[j * DIM + tid] = ci[j]; }
    }
    __syncthreads();

    // ---- stage 2: B_i[k][kp] = Σ_j s_ij (Ur_jk Ur_jkp + Ui_jk Ui_jkp) ----
    for (int idx = tid; idx < 4 * 256; idx += 128) {
        const int i  = idx >> 8;
        const int k  = (idx >> 4) & 15;
        const int kp = idx & 15;
        float sum = 0.0f;
#pragma unroll
        for (int j = 0; j < DIM; ++j) {
            float t = sUr[j * DIM + k] * sUr[j * DIM + kp]
                    + sUi[j * DIM + k] * sUi[j * DIM + kp];
            sum += ((j >> (3 - i)) & 1) ? -t : t;
        }
        sA[idx] = sum;
    }
    __syncthreads();

    // ---- stage 3: 4 separable sweeps (qubit q on MSB of remaining bits).
    // out[0]=in(0,0)+in(1,1); out[1]=in(0,0)-in(1,1); out[2]=in(0,1)+in(1,0).
    {
        float* bufs[2] = { sA, sC };
#pragma unroll
        for (int s = 0; s < 4; ++s) {
            const float* in   = bufs[s & 1];
            float*       outb = bufs[(s + 1) & 1];
            const int pow3 = (s == 0) ? 1 : (s == 1) ? 3 : (s == 2) ? 9 : 27;
            const int R    = 4 - s;
            const int half = 1 << (R - 1);
            const int full = 1 << R;
            const int nOut = 4 * pow3 * 3 * half * half;
            for (int o = tid; o < nOut; o += 128) {
                int t = o;
                const int kp_r = t % half;  t /= half;
                const int k_r  = t % half;  t /= half;
                const int mq   = t % 3;     t /= 3;
                const int m    = t % pow3;  t /= pow3;
                const int i    = t;
                const int base = ((i * pow3 + m) * full) * full;
                const int i00 = base + (0 * half + k_r) * full + (0 * half + kp_r);
                const int i11 = base + (1 * half + k_r) * full + (1 * half + kp_r);
                const int i01 = base + (0 * half + k_r) * full + (1 * half + kp_r);
                const int i10 = base + (1 * half + k_r) * full + (0 * half + kp_r);
                float v;
                if (mq == 0)      v = in[i00] + in[i11];
                else if (mq == 1) v = in[i00] - in[i11];
                else              v = in[i01] + in[i10];
                outb[o] = v;
            }
            __syncthreads();
        }
    }
    // final data in sA: (i*81 + m), m = a*9 + b.

    // ---- stage 4: padded dup'd ul2 rows; T = sA / 16 ----
    for (int slot = tid; slot < 4 * 9 * ROWW; slot += 128) {
        const int j = slot % ROWW;
        const int a = (slot / ROWW) % 9;
        const int i = slot / (ROWW * 9);
        const int b0 = 2 * j, b1 = 2 * j + 1;
        const float t0 = sA[i * NBASIS + a * 9 + b0] * 0.0625f;
        const float t1 = (b1 < 9) ? sA[i * NBASIS + a * 9 + b1] * 0.0625f : 0.0f;
        ulonglong2 u; u.x = pk(t0, t0); u.y = pk(t1, t1);
        g_T2[((h * 4 + i) * 9 + a) * ROWW + j] = u;
    }
}

// ---- build the 9-element monomial vectors for one token pair --------------
__device__ __forceinline__ void make_monomials(const float4& aa, const float4& ab,
                                               ull* m01, ull* m23) {
    float c0a, s0a, c0b, s0b, c1a, s1a, c1b, s1b;
    float c2a, s2a, c2b, s2b, c3a, s3a, c3b, s3b;
    __sincosf(aa.x, &s0a, &c0a);  __sincosf(ab.x, &s0b, &c0b);
    __sincosf(aa.y, &s1a, &c1a);  __sincosf(ab.y, &s1b, &c1b);
    __sincosf(aa.z, &s2a, &c2a);  __sincosf(ab.z, &s2b, &c2b);
    __sincosf(aa.w, &s3a, &c3a);  __sincosf(ab.w, &s3b, &c3b);
    const ull C0 = pk(c0a, c0b), S0 = pk(s0a, s0b);
    const ull C1 = pk(c1a, c1b), S1 = pk(s1a, s1b);
    const ull C2 = pk(c2a, c2b), S2 = pk(s2a, s2b);
    const ull C3 = pk(c3a, c3b), S3 = pk(s3a, s3b);
    m01[1] = C1;            m01[2] = S1;
    m01[3] = C0;            m01[6] = S0;
    m01[4] = f2mul(C0, C1); m01[5] = f2mul(C0, S1);
    m01[7] = f2mul(S0, C1); m01[8] = f2mul(S0, S1);
    m23[1] = C3;            m23[2] = S3;
    m23[3] = C2;            m23[6] = S2;
    m23[4] = f2mul(C2, C3); m23[5] = f2mul(C2, S3);
    m23[7] = f2mul(S2, C3); m23[8] = f2mul(S2, S3);
}

// ============================================================================
// Kernel 2 (FUSED, 4 tokens/thread): ev + output projection.
// Pair0 = tokens (t0, t0+1), pair1 = (t0+2, t0+3). T loads shared via dual
// accumulation. Pair0 projected inline (32 packed register accumulators);
// pair1 ev staged in smem [f][tid] (conflict-free, same-thread RAW) and
// projected in a second pass reusing the accumulator registers.
// ============================================================================
__global__ __launch_bounds__(BLK) void fused_kernel(const float* __restrict__ x,
                                                    const float* __restrict__ W,
                                                    const float* __restrict__ bvec,
                                                    float* __restrict__ out) {
    __shared__ ulonglong2 sT2[NROWS * ROWW];   // 22.5 KB
    __shared__ ulonglong2 sWc[EMB * 16];       // 8 KB: [f][ep] = {dup W[2ep][f], dup W[2ep+1][f]}
    __shared__ ull        sEv[EMB * BLK];      // 16 KB: pair1 ev staging, [f][tid]
    __shared__ float      sb[EMB];

    for (int i = threadIdx.x; i < NROWS * ROWW; i += BLK) sT2[i] = g_T2[i];
    for (int i = threadIdx.x; i < EMB * 16; i += BLK) {
        const int f = i >> 4, ep = i & 15;
        ulonglong2 u;
        const float w0 = W[(2 * ep) * EMB + f], w1 = W[(2 * ep + 1) * EMB + f];
        u.x = pk(w0, w0); u.y = pk(w1, w1);
        sWc[i] = u;
    }
    if (threadIdx.x < EMB) sb[threadIdx.x] = bvec[threadIdx.x];
    __syncthreads();

    const int tid = threadIdx.x;
    const int gid = blockIdx.x * BLK + tid;
    const int t0  = gid * 4;

    // 32 packed output accumulators for pair0 (token t0 lo, t0+1 hi)
    ull acc[EMB];
#pragma unroll
    for (int e = 0; e < EMB; ++e) { const float be = sb[e]; acc[e] = pk(be, be); }

#pragma unroll 1
    for (int h = 0; h < NH; ++h) {
        // ---- angles for 4 tokens -> monomials for both pairs ----
        float4 a0 = *reinterpret_cast<const float4*>(x + (size_t)t0 * EMB + h * 4);
        float4 a1 = *reinterpret_cast<const float4*>(x + (size_t)(t0 + 1) * EMB + h * 4);
        float4 a2 = *reinterpret_cast<const float4*>(x + (size_t)(t0 + 2) * EMB + h * 4);
        float4 a3 = *reinterpret_cast<const float4*>(x + (size_t)(t0 + 3) * EMB + h * 4);
        ull m01p0[9], m23p0[9], m01p1[9], m23p1[9];
        make_monomials(a0, a1, m01p0, m23p0);
        make_monomials(a2, a3, m01p1, m23p1);

#pragma unroll
        for (int i = 0; i < 4; ++i) {
            // ---- dual 9x9 factored dot: T loads shared across both pairs ----
            const ulonglong2* Ti = sT2 + ((h * 4 + i) * 9) * ROWW;
            ull ev0, ev1;
#pragma unroll
            for (int a = 0; a < 9; ++a) {
                const ulonglong2* Tr = Ti + a * ROWW;
                ulonglong2 w = Tr[0];                  // {dup T0, dup T1}
                ull ta0 = f2fma(w.y, m23p0[1], w.x);
                ull ta1 = f2fma(w.y, m23p1[1], w.x);
#pragma unroll
                for (int j = 1; j < 4; ++j) {
                    w = Tr[j];                         // {dup T(2j), dup T(2j+1)}
                    ta0 = f2fma(w.x, m23p0[2 * j],     ta0);
                    ta0 = f2fma(w.y, m23p0[2 * j + 1], ta0);
                    ta1 = f2fma(w.x, m23p1[2 * j],     ta1);
                    ta1 = f2fma(w.y, m23p1[2 * j + 1], ta1);
                }
                w = Tr[4];                             // {dup T8, 0}
                ta0 = f2fma(w.x, m23p0[8], ta0);
                ta1 = f2fma(w.x, m23p1[8], ta1);
                if (a == 0) { ev0 = ta0; ev1 = ta1; }  // m01[0] = 1
                else {
                    ev0 = f2fma(ta0, m01p0[a], ev0);
                    ev1 = f2fma(ta1, m01p1[a], ev1);
                }
            }
            // ---- pair0: incremental projection into register accumulators ----
            const ulonglong2* Wf = sWc + (h * 4 + i) * 16;
#pragma unroll
            for (int ep = 0; ep < 16; ++ep) {
                ulonglong2 w = Wf[ep];
                acc[2 * ep]     = f2fma(w.x, ev0, acc[2 * ep]);
                acc[2 * ep + 1] = f2fma(w.y, ev0, acc[2 * ep + 1]);
            }
            // ---- pair1: stage ev in smem (read back by the SAME thread) ----
            sEv[(h * 4 + i) * BLK + tid] = ev1;
        }
    }

    // ---- store pair0 tokens ----
#pragma unroll
    for (int eg = 0; eg < 8; ++eg) {
        float o0[4], o1[4];
#pragma unroll
        for (int r = 0; r < 4; ++r) upk(acc[eg * 4 + r], o0[r], o1[r]);
        *reinterpret_cast<float4*>(out + (size_t)t0 * EMB + eg * 4)       = make_float4(o0[0], o0[1], o0[2], o0[3]);
        *reinterpret_cast<float4*>(out + (size_t)(t0 + 1) * EMB + eg * 4) = make_float4(o1[0], o1[1], o1[2], o1[3]);
    }

    // ---- pair1 projection pass (reuse accumulator registers) ----
#pragma unroll
    for (int e = 0; e < EMB; ++e) { const float be = sb[e]; acc[e] = pk(be, be); }
#pragma unroll 1
    for (int f = 0; f < EMB; ++f) {
        const ull evi = sEv[f * BLK + tid];
        const ulonglong2* Wf = sWc + f * 16;
#pragma unroll
        for (int ep = 0; ep < 16; ++ep) {
            ulonglong2 w = Wf[ep];
            acc[2 * ep]     = f2fma(w.x, evi, acc[2 * ep]);
            acc[2 * ep + 1] = f2fma(w.y, evi, acc[2 * ep + 1]);
        }
    }
#pragma unroll
    for (int eg = 0; eg < 8; ++eg) {
        float o0[4], o1[4];
#pragma unroll
        for (int r = 0; r < 4; ++r) upk(acc[eg * 4 + r], o0[r], o1[r]);
        *reinterpret_cast<float4*>(out + (size_t)(t0 + 2) * EMB + eg * 4) = make_float4(o0[0], o0[1], o0[2], o0[3]);
        *reinterpret_cast<float4*>(out + (size_t)(t0 + 3) * EMB + eg * 4) = make_float4(o1[0], o1[1], o1[2], o1[3]);
    }
}

// ============================================================================
extern "C" void kernel_launch(void* const* d_in, const int* in_sizes, int n_in,
                              void* d_out, int out_size) {
    // Identify inputs by element count (all distinct):
    // x: 4194304, params: 192, W_out: 1024, b_out: 32
    const float* x = 0; const float* params = 0; const float* W = 0; const float* b = 0;
    for (int i = 0; i < n_in; ++i) {
        switch (in_sizes[i]) {
            case 4194304: x      = (const float*)d_in[i]; break;
            case 192:     params = (const float*)d_in[i]; break;
            case 1024:    W      = (const float*)d_in[i]; break;
            case 32:      b      = (const float*)d_in[i]; break;
            default: break;
        }
    }
    float* out = (float*)d_out;

    precompute_T_kernel<<<NH, 128>>>(params);
    fused_kernel<<<512, BLK>>>(x, W, b, out);   // 32768 threads * 4 tokens
}

// round 16
// speedup vs baseline: 1.5006x; 1.5006x over previous
#include <cuda_runtime.h>

// ============================================================================
// MultiHeadAttentionQuantum — algebraic form.
// ev_i = Σ_{a,b} T_i[a][b] m01[a] m23[b]  (81-term multilinear basis in
// {1,cos x_q,sin x_q});  out = W ev + b.
// Round-15 lesson: broadcast LDS.128 moves 512B/warp through the L1 crossbar
// (4 wavefronts) — duplicated-data tables waste half the binding resource.
// This version stores T NON-duplicated (9 wf/row instead of 20), duplicates
// into f32x2 lanes via MOVs on the idle ALU pipe, amortizes each row over
// 4 tokens (2 packed pairs), and splits heads across threads (2 heads/thread)
// to keep 131072 threads (6.9 warps/SMSP) with ~110 regs — no spills.
// ============================================================================

#define NQ      4
#define DIM     16
#define NH      8
#define NLAYERS 2
#define EMB     32
#define NTOK    (32 * 4096)
#define NPAIR   (NTOK / 2)
#define NBASIS  81
#define NROWS   (NH * 4 * 9)          // 288 T-rows (h, i, a)
#define RPAD    12                     // floats per padded row (9 + 3 pad)

typedef unsigned long long ull;

// ---- packed f32x2 helpers (Blackwell sm_103a) ------------------------------
__device__ __forceinline__ ull pk(float lo, float hi) {
    ull r; asm("mov.b64 %0, {%1, %2};" : "=l"(r) : "f"(lo), "f"(hi)); return r;
}
__device__ __forceinline__ void upk(ull v, float& lo, float& hi) {
    asm("mov.b64 {%0, %1}, %2;" : "=f"(lo), "=f"(hi) : "l"(v));
}
__device__ __forceinline__ ull f2mul(ull a, ull b) {
    ull d; asm("mul.rn.f32x2 %0, %1, %2;" : "=l"(d) : "l"(a), "l"(b)); return d;
}
__device__ __forceinline__ ull f2fma(ull a, ull b, ull c) {
    ull d; asm("fma.rn.f32x2 %0, %1, %2, %3;" : "=l"(d) : "l"(a), "l"(b), "l"(c)); return d;
}

// ---- global scratch (static device arrays; no allocation) ------------------
__device__ float g_Tp[NROWS * RPAD];            // plain f32 T rows, padded to 12
__device__ ull   g_evP[(size_t)NPAIR * EMB];    // 16 MB: packed ev pairs [pair][f]

// ============================================================================
// Gate helpers with COMPILE-TIME masks (static register indexing).
// ============================================================================
template<int M>
__device__ __forceinline__ void rot3(float* cr, float* ci, const float* p) {
    float c, s;
    __sincosf(0.5f * p[0], &s, &c);          // RX
#pragma unroll
    for (int j = 0; j < DIM; ++j) if (!(j & M)) {
        const int j1 = j | M;
        float a0r = cr[j],  a0i = ci[j];
        float a1r = cr[j1], a1i = ci[j1];
        cr[j]  = c * a0r + s * a1i;   ci[j]  = c * a0i - s * a1r;
        cr[j1] = c * a1r + s * a0i;   ci[j1] = c * a1i - s * a0r;
    }
    __sincosf(0.5f * p[1], &s, &c);          // RY
#pragma unroll
    for (int j = 0; j < DIM; ++j) if (!(j & M)) {
        const int j1 = j | M;
        float a0r = cr[j],  a0i = ci[j];
        float a1r = cr[j1], a1i = ci[j1];
        cr[j]  = c * a0r - s * a1r;   ci[j]  = c * a0i - s * a1i;
        cr[j1] = s * a0r + c * a1r;   ci[j1] = s * a0i + c * a1i;
    }
    __sincosf(0.5f * p[2], &s, &c);          // RZ
#pragma unroll
    for (int j = 0; j < DIM; ++j) if (!(j & M)) {
        const int j1 = j | M;
        float a0r = cr[j],  a0i = ci[j];
        float a1r = cr[j1], a1i = ci[j1];
        cr[j]  = c * a0r + s * a0i;   ci[j]  = c * a0i - s * a0r;
        cr[j1] = c * a1r - s * a1i;   ci[j1] = c * a1i + s * a1r;
    }
}

template<int CM, int TM>
__device__ __forceinline__ void cnot_g(float* cr, float* ci) {
#pragma unroll
    for (int j = 0; j < DIM; ++j) if ((j & CM) && !(j & TM)) {
        const int j1 = j | TM;
        float tr = cr[j]; cr[j] = cr[j1]; cr[j1] = tr;
        float ti = ci[j]; ci[j] = ci[j1]; ci[j1] = ti;
    }
}

// ============================================================================
// Kernel 1: per head, build U -> B_i -> T via SEPARABLE qubit sweeps.
// One block per head (8 blocks x 128 threads), params staged via smem.
// ============================================================================
__global__ void precompute_T_kernel(const float* __restrict__ params) {
    __shared__ float sPar[NLAYERS * NQ * 3];
    __shared__ float sUr[DIM * DIM], sUi[DIM * DIM];
    __shared__ float sA[4 * 256];    // ping
    __shared__ float sC[4 * 192];    // pong (max intermediate = 768)
    const int h   = blockIdx.x;
    const int tid = threadIdx.x;

    if (tid < NLAYERS * NQ * 3) sPar[tid] = params[h * NLAYERS * NQ * 3 + tid];
    __syncthreads();

    // ---- stage 1: threads 0..15 each evolve one COLUMN of U ----
    if (tid < DIM) {
        float cr[DIM], ci[DIM];
#pragma unroll
        for (int j = 0; j < DIM; ++j) { cr[j] = (j == tid) ? 1.0f : 0.0f; ci[j] = 0.0f; }
#pragma unroll
        for (int l = 0; l < NLAYERS; ++l) {
            const float* pb = sPar + l * NQ * 3;
            rot3<8>(cr, ci, pb + 0);
            rot3<4>(cr, ci, pb + 3);
            rot3<2>(cr, ci, pb + 6);
            rot3<1>(cr, ci, pb + 9);
            cnot_g<8, 4>(cr, ci);
            cnot_g<4, 2>(cr, ci);
            cnot_g<2, 1>(cr, ci);
            cnot_g<1, 8>(cr, ci);
        }
#pragma unroll
        for (int j = 0; j < DIM; ++j) { sUr[j * DIM + tid] = cr[j]; sUi[j * DIM + tid] = ci[j]; }
    }
    __syncthreads();

    // ---- stage 2: B_i[k][kp] = Σ_j s_ij (Ur_jk Ur_jkp + Ui_jk Ui_jkp) ----
    for (int idx = tid; idx < 4 * 256; idx += 128) {
        const int i  = idx >> 8;
        const int k  = (idx >> 4) & 15;
        const int kp = idx & 15;
        float sum = 0.0f;
#pragma unroll
        for (int j = 0; j < DIM; ++j) {
            float t = sUr[j * DIM + k] * sUr[j * DIM + kp]
                    + sUi[j * DIM + k] * sUi[j * DIM + kp];
            sum += ((j >> (3 - i)) & 1) ? -t : t;
        }
        sA[idx] = sum;
    }
    __syncthreads();

    // ---- stage 3: 4 separable sweeps (qubit q on MSB of remaining bits).
    // out[0]=in(0,0)+in(1,1); out[1]=in(0,0)-in(1,1); out[2]=in(0,1)+in(1,0).
    {
        float* bufs[2] = { sA, sC };
#pragma unroll
        for (int s = 0; s < 4; ++s) {
            const float* in   = bufs[s & 1];
            float*       outb = bufs[(s + 1) & 1];
            const int pow3 = (s == 0) ? 1 : (s == 1) ? 3 : (s == 2) ? 9 : 27;
            const int R    = 4 - s;
            const int half = 1 << (R - 1);
            const int full = 1 << R;
            const int nOut = 4 * pow3 * 3 * half * half;
            for (int o = tid; o < nOut; o += 128) {
                int t = o;
                const int kp_r = t % half;  t /= half;
                const int k_r  = t % half;  t /= half;
                const int mq   = t % 3;     t /= 3;
                const int m    = t % pow3;  t /= pow3;
                const int i    = t;
                const int base = ((i * pow3 + m) * full) * full;
                const int i00 = base + (0 * half + k_r) * full + (0 * half + kp_r);
                const int i11 = base + (1 * half + k_r) * full + (1 * half + kp_r);
                const int i01 = base + (0 * half + k_r) * full + (1 * half + kp_r);
                const int i10 = base + (1 * half + k_r) * full + (0 * half + kp_r);
                float v;
                if (mq == 0)      v = in[i00] + in[i11];
                else if (mq == 1) v = in[i00] - in[i11];
                else              v = in[i01] + in[i10];
                outb[o] = v;
            }
            __syncthreads();
        }
    }
    // final data in sA: (i*81 + m), m = a*9 + b.

    // ---- stage 4: plain padded rows; T = sA / 16 ----
    for (int idx = tid; idx < 4 * 9 * RPAD; idx += 128) {
        const int b = idx % RPAD;
        const int a = (idx / RPAD) % 9;
        const int i = idx / (RPAD * 9);
        const float v = (b < 9) ? sA[i * NBASIS + a * 9 + b] * 0.0625f : 0.0f;
        g_Tp[((h * 4 + i) * 9 + a) * RPAD + b] = v;
    }
}

// ---- build the 9-element monomial vectors for one token pair --------------
__device__ __forceinline__ void make_monomials(const float4& aa, const float4& ab,
                                               ull* m01, ull* m23) {
    float c0a, s0a, c0b, s0b, c1a, s1a, c1b, s1b;
    float c2a, s2a, c2b, s2b, c3a, s3a, c3b, s3b;
    __sincosf(aa.x, &s0a, &c0a);  __sincosf(ab.x, &s0b, &c0b);
    __sincosf(aa.y, &s1a, &c1a);  __sincosf(ab.y, &s1b, &c1b);
    __sincosf(aa.z, &s2a, &c2a);  __sincosf(ab.z, &s2b, &c2b);
    __sincosf(aa.w, &s3a, &c3a);  __sincosf(ab.w, &s3b, &c3b);
    const ull C0 = pk(c0a, c0b), S0 = pk(s0a, s0b);
    const ull C1 = pk(c1a, c1b), S1 = pk(s1a, s1b);
    const ull C2 = pk(c2a, c2b), S2 = pk(s2a, s2b);
    const ull C3 = pk(c3a, c3b), S3 = pk(s3a, s3b);
    m01[1] = C1;            m01[2] = S1;
    m01[3] = C0;            m01[6] = S0;
    m01[4] = f2mul(C0, C1); m01[5] = f2mul(C0, S1);
    m01[7] = f2mul(S0, C1); m01[8] = f2mul(S0, S1);
    m23[1] = C3;            m23[2] = S3;
    m23[3] = C2;            m23[6] = S2;
    m23[4] = f2mul(C2, C3); m23[5] = f2mul(C2, S3);
    m23[7] = f2mul(S2, C3); m23[8] = f2mul(S2, S3);
}

// ============================================================================
// Kernel 2: ev. Thread = (token-quad, head-pair): 4 tokens x 2 heads.
// 131072 threads (1024 blocks x 128). Warp w of each block owns head-pair w
// so ALL T loads are warp-uniform broadcasts. T rows non-dup (9 wf) and each
// row's dup-MOVs (ALU pipe) are amortized over both packed pairs.
// Writes packed ev pairs to g_evP[pair][f].
// ============================================================================
__global__ __launch_bounds__(128) void ev_kernel(const float* __restrict__ x) {
    __shared__ float sT[NROWS * RPAD];   // 13.5 KB
    for (int i = threadIdx.x; i < NROWS * RPAD / 4; i += 128)
        reinterpret_cast<float4*>(sT)[i] = reinterpret_cast<const float4*>(g_Tp)[i];
    __syncthreads();

    const int hp   = threadIdx.x >> 5;            // head-pair 0..3 (per warp)
    const int lane = threadIdx.x & 31;
    const int quad = blockIdx.x * 32 + lane;      // 0..32767
    const int t0   = quad * 4;
    const size_t pbase = (size_t)quad * 2 * EMB;  // pair p0 = quad*2

#pragma unroll
    for (int hh = 0; hh < 2; ++hh) {
        const int h = hp * 2 + hh;
        // angles for 4 tokens, this head
        float4 a0 = *reinterpret_cast<const float4*>(x + (size_t)t0 * EMB + h * 4);
        float4 a1 = *reinterpret_cast<const float4*>(x + (size_t)(t0 + 1) * EMB + h * 4);
        float4 a2 = *reinterpret_cast<const float4*>(x + (size_t)(t0 + 2) * EMB + h * 4);
        float4 a3 = *reinterpret_cast<const float4*>(x + (size_t)(t0 + 3) * EMB + h * 4);
        ull m01p0[9], m23p0[9], m01p1[9], m23p1[9];
        make_monomials(a0, a1, m01p0, m23p0);
        make_monomials(a2, a3, m01p1, m23p1);

#pragma unroll
        for (int i4 = 0; i4 < 4; ++i4) {
            const float* Tb = sT + ((h * 4 + i4) * 9) * RPAD;
            ull ev0, ev1;
#pragma unroll
            for (int a = 0; a < 9; ++a) {
                const float* r = Tb + a * RPAD;
                float4 ra = *reinterpret_cast<const float4*>(r);       // T0..T3
                float4 rb = *reinterpret_cast<const float4*>(r + 4);   // T4..T7
                float  rc = r[8];                                      // T8
                // dup to f32x2 on ALU pipe; reused by both pairs
                const ull T0 = pk(ra.x, ra.x), T1 = pk(ra.y, ra.y);
                const ull T2 = pk(ra.z, ra.z), T3 = pk(ra.w, ra.w);
                const ull T4 = pk(rb.x, rb.x), T5 = pk(rb.y, rb.y);
                const ull T6 = pk(rb.z, rb.z), T7 = pk(rb.w, rb.w);
                const ull T8 = pk(rc, rc);
                ull ta0 = f2fma(T1, m23p0[1], T0);
                ta0 = f2fma(T2, m23p0[2], ta0);
                ta0 = f2fma(T3, m23p0[3], ta0);
                ta0 = f2fma(T4, m23p0[4], ta0);
                ta0 = f2fma(T5, m23p0[5], ta0);
                ta0 = f2fma(T6, m23p0[6], ta0);
                ta0 = f2fma(T7, m23p0[7], ta0);
                ta0 = f2fma(T8, m23p0[8], ta0);
                ull ta1 = f2fma(T1, m23p1[1], T0);
                ta1 = f2fma(T2, m23p1[2], ta1);
                ta1 = f2fma(T3, m23p1[3], ta1);
                ta1 = f2fma(T4, m23p1[4], ta1);
                ta1 = f2fma(T5, m23p1[5], ta1);
                ta1 = f2fma(T6, m23p1[6], ta1);
                ta1 = f2fma(T7, m23p1[7], ta1);
                ta1 = f2fma(T8, m23p1[8], ta1);
                if (a == 0) { ev0 = ta0; ev1 = ta1; }      // m01[0] = 1
                else {
                    ev0 = f2fma(ta0, m01p0[a], ev0);
                    ev1 = f2fma(ta1, m01p1[a], ev1);
                }
            }
            g_evP[pbase + (h * 4 + i4)]       = ev0;   // pair p0
            g_evP[pbase + EMB + (h * 4 + i4)] = ev1;   // pair p0+1
        }
    }
}

// ============================================================================
// Kernel 3: out[t] = W ev[t] + b. Thread = one pair; scalar FFMA (no dup
// MOVs), W plain f32 in smem (float4 broadcast = half the wavefronts of the
// dup'd layout). ev pair rows read coalesced from g_evP.
// ============================================================================
__global__ __launch_bounds__(128) void out_kernel(const float* __restrict__ W,
                                                  const float* __restrict__ bvec,
                                                  float* __restrict__ out) {
    __shared__ float sW[EMB * EMB];   // 4 KB, row-major W[e][f]
    __shared__ float sb[EMB];
    for (int i = threadIdx.x; i < EMB * EMB / 4; i += 128)
        reinterpret_cast<float4*>(sW)[i] = reinterpret_cast<const float4*>(W)[i];
    if (threadIdx.x < EMB) sb[threadIdx.x] = bvec[threadIdx.x];
    __syncthreads();

    const int p  = blockIdx.x * 128 + threadIdx.x;   // pair id, 0..65535
    const int t0 = p * 2;

    // load 32 packed ev values = 64 floats: ev[2f] = token t0, ev[2f+1] = t0+1
    float ev[64];
    const float4* evp = reinterpret_cast<const float4*>(g_evP + (size_t)p * EMB);
#pragma unroll
    for (int i = 0; i < 16; ++i) {
        float4 v = evp[i];
        ev[4 * i + 0] = v.x; ev[4 * i + 1] = v.y;
        ev[4 * i + 2] = v.z; ev[4 * i + 3] = v.w;
    }

#pragma unroll
    for (int eg = 0; eg < 8; ++eg) {
        float o0[4], o1[4];
#pragma unroll
        for (int r = 0; r < 4; ++r) {
            const int e = eg * 4 + r;
            float alo = sb[e], ahi = alo;
            const float4* wr = reinterpret_cast<const float4*>(sW + e * EMB);
#pragma unroll
            for (int k = 0; k < 8; ++k) {
                float4 w = wr[k];
                alo = fmaf(w.x, ev[8 * k + 0], alo);  ahi = fmaf(w.x, ev[8 * k + 1], ahi);
                alo = fmaf(w.y, ev[8 * k + 2], alo);  ahi = fmaf(w.y, ev[8 * k + 3], ahi);
                alo = fmaf(w.z, ev[8 * k + 4], alo);  ahi = fmaf(w.z, ev[8 * k + 5], ahi);
                alo = fmaf(w.w, ev[8 * k + 6], alo);  ahi = fmaf(w.w, ev[8 * k + 7], ahi);
            }
            o0[r] = alo; o1[r] = ahi;
        }
        *reinterpret_cast<float4*>(out + (size_t)t0 * EMB + eg * 4)       = make_float4(o0[0], o0[1], o0[2], o0[3]);
        *reinterpret_cast<float4*>(out + (size_t)(t0 + 1) * EMB + eg * 4) = make_float4(o1[0], o1[1], o1[2], o1[3]);
    }
}

// ============================================================================
extern "C" void kernel_launch(void* const* d_in, const int* in_sizes, int n_in,
                              void* d_out, int out_size) {
    // Identify inputs by element count (all distinct):
    // x: 4194304, params: 192, W_out: 1024, b_out: 32
    const float* x = 0; const float* params = 0; const float* W = 0; const float* b = 0;
    for (int i = 0; i < n_in; ++i) {
        switch (in_sizes[i]) {
            case 4194304: x      = (const float*)d_in[i]; break;
            case 192:     params = (const float*)d_in[i]; break;
            case 1024:    W      = (const float*)d_in[i]; break;
            case 32:      b      = (const float*)d_in[i]; break;
            default: break;
        }
    }
    float* out = (float*)d_out;

    precompute_T_kernel<<<NH, 128>>>(params);
    ev_kernel<<<1024, 128>>>(x);          // 131072 threads: 4 tokens x 2 heads each
    out_kernel<<<512, 128>>>(W, b, out);  // 65536 threads: 1 pair each
}

// round 17
// speedup vs baseline: 1.9728x; 1.3146x over previous
#include <cuda_runtime.h>

// ============================================================================
// MultiHeadAttentionQuantum — algebraic form, single fused main kernel.
// ev_i = Σ_{a,b} T_i[a][b] m01[a] m23[b]  (81-term multilinear basis in
// {1,cos x_q,sin x_q});  out = W ev + b.
// Phase A (warp = head-pair, lane = token-quad): factored 9x9 dots with
// non-duplicated T rows (dup to f32x2 on the idle ALU pipe), writing packed
// ev pairs into a 16 KB smem tile. One __syncthreads. Phase B: register-
// tiled 32x32 projection — thread owns 4 tokens x 8 outputs, W streamed as
// scalar float4 and ALU-dup'd, each load amortized over 4 tokens. No 32 MB
// ev round trip, no third kernel, no warp-uniform W broadcast per 2 FMAs.
// ============================================================================

#define NQ      4
#define DIM     16
#define NH      8
#define NLAYERS 2
#define EMB     32
#define NTOK    (32 * 4096)
#define NBASIS  81
#define NROWS   (NH * 4 * 9)          // 288 T-rows (h, i, a)
#define RPAD    12                     // floats per padded T row (9 + 3 pad)

typedef unsigned long long ull;

// ---- packed f32x2 helpers (Blackwell sm_103a) ------------------------------
__device__ __forceinline__ ull pk(float lo, float hi) {
    ull r; asm("mov.b64 %0, {%1, %2};" : "=l"(r) : "f"(lo), "f"(hi)); return r;
}
__device__ __forceinline__ void upk(ull v, float& lo, float& hi) {
    asm("mov.b64 {%0, %1}, %2;" : "=f"(lo), "=f"(hi) : "l"(v));
}
__device__ __forceinline__ ull f2mul(ull a, ull b) {
    ull d; asm("mul.rn.f32x2 %0, %1, %2;" : "=l"(d) : "l"(a), "l"(b)); return d;
}
__device__ __forceinline__ ull f2fma(ull a, ull b, ull c) {
    ull d; asm("fma.rn.f32x2 %0, %1, %2, %3;" : "=l"(d) : "l"(a), "l"(b), "l"(c)); return d;
}

// ---- global scratch (static device array; no allocation) -------------------
__device__ float g_Tp[NROWS * RPAD];   // plain f32 T rows, padded to 12

// ============================================================================
// Gate helpers with COMPILE-TIME masks (static register indexing).
// ============================================================================
template<int M>
__device__ __forceinline__ void rot3(float* cr, float* ci, const float* p) {
    float c, s;
    __sincosf(0.5f * p[0], &s, &c);          // RX
#pragma unroll
    for (int j = 0; j < DIM; ++j) if (!(j & M)) {
        const int j1 = j | M;
        float a0r = cr[j],  a0i = ci[j];
        float a1r = cr[j1], a1i = ci[j1];
        cr[j]  = c * a0r + s * a1i;   ci[j]  = c * a0i - s * a1r;
        cr[j1] = c * a1r + s * a0i;   ci[j1] = c * a1i - s * a0r;
    }
    __sincosf(0.5f * p[1], &s, &c);          // RY
#pragma unroll
    for (int j = 0; j < DIM; ++j) if (!(j & M)) {
        const int j1 = j | M;
        float a0r = cr[j],  a0i = ci[j];
        float a1r = cr[j1], a1i = ci[j1];
        cr[j]  = c * a0r - s * a1r;   ci[j]  = c * a0i - s * a1i;
        cr[j1] = s * a0r + c * a1r;   ci[j1] = s * a0i + c * a1i;
    }
    __sincosf(0.5f * p[2], &s, &c);          // RZ
#pragma unroll
    for (int j = 0; j < DIM; ++j) if (!(j & M)) {
        const int j1 = j | M;
        float a0r = cr[j],  a0i = ci[j];
        float a1r = cr[j1], a1i = ci[j1];
        cr[j]  = c * a0r + s * a0i;   ci[j]  = c * a0i - s * a0r;
        cr[j1] = c * a1r - s * a1i;   ci[j1] = c * a1i + s * a1r;
    }
}

template<int CM, int TM>
__device__ __forceinline__ void cnot_g(float* cr, float* ci) {
#pragma unroll
    for (int j = 0; j < DIM; ++j) if ((j & CM) && !(j & TM)) {
        const int j1 = j | TM;
        float tr = cr[j]; cr[j] = cr[j1]; cr[j1] = tr;
        float ti = ci[j]; ci[j] = ci[j1]; ci[j1] = ti;
    }
}

// ============================================================================
// Kernel 1: per head, build U -> B_i -> T via SEPARABLE qubit sweeps.
// One block per head. Stage 2 computes all 4 B_i per (k,kp) cell at once
// (products computed once, 4 signed adds) — 4x less LDS than the old form.
// ============================================================================
__global__ void precompute_T_kernel(const float* __restrict__ params) {
    __shared__ float sPar[NLAYERS * NQ * 3];
    __shared__ float sUr[DIM * DIM], sUi[DIM * DIM];
    __shared__ float sA[4 * 256];    // ping
    __shared__ float sC[4 * 192];    // pong (max intermediate = 768)
    const int h   = blockIdx.x;
    const int tid = threadIdx.x;

    if (tid < NLAYERS * NQ * 3) sPar[tid] = params[h * NLAYERS * NQ * 3 + tid];
    __syncthreads();

    // ---- stage 1: threads 0..15 each evolve one COLUMN of U ----
    if (tid < DIM) {
        float cr[DIM], ci[DIM];
#pragma unroll
        for (int j = 0; j < DIM; ++j) { cr[j] = (j == tid) ? 1.0f : 0.0f; ci[j] = 0.0f; }
#pragma unroll
        for (int l = 0; l < NLAYERS; ++l) {
            const float* pb = sPar + l * NQ * 3;
            rot3<8>(cr, ci, pb + 0);
            rot3<4>(cr, ci, pb + 3);
            rot3<2>(cr, ci, pb + 6);
            rot3<1>(cr, ci, pb + 9);
            cnot_g<8, 4>(cr, ci);
            cnot_g<4, 2>(cr, ci);
            cnot_g<2, 1>(cr, ci);
            cnot_g<1, 8>(cr, ci);
        }
#pragma unroll
        for (int j = 0; j < DIM; ++j) { sUr[j * DIM + tid] = cr[j]; sUi[j * DIM + tid] = ci[j]; }
    }
    __syncthreads();

    // ---- stage 2: all 4 B_i per cell (k,kp); 2 cells/thread ----
#pragma unroll
    for (int c = 0; c < 2; ++c) {
        const int cell = tid + c * 128;          // 0..255
        const int k  = cell >> 4;
        const int kp = cell & 15;
        float a0 = 0.f, a1 = 0.f, a2 = 0.f, a3 = 0.f;
#pragma unroll
        for (int j = 0; j < DIM; ++j) {
            const float t = sUr[j * DIM + k] * sUr[j * DIM + kp]
                          + sUi[j * DIM + k] * sUi[j * DIM + kp];
            a0 += (j & 8) ? -t : t;
            a1 += (j & 4) ? -t : t;
            a2 += (j & 2) ? -t : t;
            a3 += (j & 1) ? -t : t;
        }
        sA[0 * 256 + cell] = a0;
        sA[1 * 256 + cell] = a1;
        sA[2 * 256 + cell] = a2;
        sA[3 * 256 + cell] = a3;
    }
    __syncthreads();

    // ---- stage 3: 4 separable sweeps (qubit q on MSB of remaining bits).
    // out[0]=in(0,0)+in(1,1); out[1]=in(0,0)-in(1,1); out[2]=in(0,1)+in(1,0).
    {
        float* bufs[2] = { sA, sC };
#pragma unroll
        for (int s = 0; s < 4; ++s) {
            const float* in   = bufs[s & 1];
            float*       outb = bufs[(s + 1) & 1];
            const int pow3 = (s == 0) ? 1 : (s == 1) ? 3 : (s == 2) ? 9 : 27;
            const int R    = 4 - s;
            const int half = 1 << (R - 1);
            const int full = 1 << R;
            const int nOut = 4 * pow3 * 3 * half * half;
            for (int o = tid; o < nOut; o += 128) {
                int t = o;
                const int kp_r = t % half;  t /= half;
                const int k_r  = t % half;  t /= half;
                const int mq   = t % 3;     t /= 3;
                const int m    = t % pow3;  t /= pow3;
                const int i    = t;
                const int base = ((i * pow3 + m) * full) * full;
                const int i00 = base + (0 * half + k_r) * full + (0 * half + kp_r);
                const int i11 = base + (1 * half + k_r) * full + (1 * half + kp_r);
                const int i01 = base + (0 * half + k_r) * full + (1 * half + kp_r);
                const int i10 = base + (1 * half + k_r) * full + (0 * half + kp_r);
                float v;
                if (mq == 0)      v = in[i00] + in[i11];
                else if (mq == 1) v = in[i00] - in[i11];
                else              v = in[i01] + in[i10];
                outb[o] = v;
            }
            __syncthreads();
        }
    }
    // final data in sA: (i*81 + m), m = a*9 + b.

    // ---- stage 4: plain padded rows; T = sA / 16 ----
    for (int idx = tid; idx < 4 * 9 * RPAD; idx += 128) {
        const int b = idx % RPAD;
        const int a = (idx / RPAD) % 9;
        const int i = idx / (RPAD * 9);
        const float v = (b < 9) ? sA[i * NBASIS + a * 9 + b] * 0.0625f : 0.0f;
        g_Tp[((h * 4 + i) * 9 + a) * RPAD + b] = v;
    }
}

// ---- build the 9-element monomial vectors for one token pair --------------
__device__ __forceinline__ void make_monomials(const float4& aa, const float4& ab,
                                               ull* m01, ull* m23) {
    float c0a, s0a, c0b, s0b, c1a, s1a, c1b, s1b;
    float c2a, s2a, c2b, s2b, c3a, s3a, c3b, s3b;
    __sincosf(aa.x, &s0a, &c0a);  __sincosf(ab.x, &s0b, &c0b);
    __sincosf(aa.y, &s1a, &c1a);  __sincosf(ab.y, &s1b, &c1b);
    __sincosf(aa.z, &s2a, &c2a);  __sincosf(ab.z, &s2b, &c2b);
    __sincosf(aa.w, &s3a, &c3a);  __sincosf(ab.w, &s3b, &c3b);
    const ull C0 = pk(c0a, c0b), S0 = pk(s0a, s0b);
    const ull C1 = pk(c1a, c1b), S1 = pk(s1a, s1b);
    const ull C2 = pk(c2a, c2b), S2 = pk(s2a, s2b);
    const ull C3 = pk(c3a, c3b), S3 = pk(s3a, s3b);
    m01[1] = C1;            m01[2] = S1;
    m01[3] = C0;            m01[6] = S0;
    m01[4] = f2mul(C0, C1); m01[5] = f2mul(C0, S1);
    m01[7] = f2mul(S0, C1); m01[8] = f2mul(S0, S1);
    m23[1] = C3;            m23[2] = S3;
    m23[3] = C2;            m23[6] = S2;
    m23[4] = f2mul(C2, C3); m23[5] = f2mul(C2, S3);
    m23[7] = f2mul(S2, C3); m23[8] = f2mul(S2, S3);
}

// ============================================================================
// Kernel 2 (FUSED): ev + output projection, one block = 128 tokens.
// Phase A: warp = head-pair, lane = token-quad. Packed ev pairs -> smem tile
//   sEv, pairLocal = lane + 32*p  (=> contiguous 16B-stride reads in phase B).
// Phase B: thread = (quad pl, e-group of 8): acc = 8e x 2pairs = 16 ull.
//   W streamed as scalar float4 (warp-uniform), dup'd via ALU pk, each W
//   value amortized over 4 tokens.
// ============================================================================
__global__ __launch_bounds__(128) void fused_kernel(const float* __restrict__ x,
                                                    const float* __restrict__ W,
                                                    const float* __restrict__ bvec,
                                                    float* __restrict__ out) {
    __shared__ float sT[NROWS * RPAD];        // 13.5 KB
    __shared__ ull   sEv[16 * 64 * 2];        // 16 KB: [(f>>1)*64 + pl]*2 + (f&1)
    __shared__ float sW[EMB * EMB];           // 4 KB, row-major W[e][f]
    __shared__ float sb[EMB];

    for (int i = threadIdx.x; i < NROWS * RPAD / 4; i += 128)
        reinterpret_cast<float4*>(sT)[i] = reinterpret_cast<const float4*>(g_Tp)[i];
    for (int i = threadIdx.x; i < EMB * EMB / 4; i += 128)
        reinterpret_cast<float4*>(sW)[i] = reinterpret_cast<const float4*>(W)[i];
    if (threadIdx.x < EMB) sb[threadIdx.x] = bvec[threadIdx.x];
    __syncthreads();

    // ======================== Phase A: ev ===================================
    {
        const int hp   = threadIdx.x >> 5;            // head-pair 0..3 (per warp)
        const int lane = threadIdx.x & 31;
        const int t0   = (blockIdx.x * 32 + lane) * 4;

#pragma unroll
        for (int hh = 0; hh < 2; ++hh) {
            const int h = hp * 2 + hh;
            float4 a0 = *reinterpret_cast<const float4*>(x + (size_t)t0 * EMB + h * 4);
            float4 a1 = *reinterpret_cast<const float4*>(x + (size_t)(t0 + 1) * EMB + h * 4);
            float4 a2 = *reinterpret_cast<const float4*>(x + (size_t)(t0 + 2) * EMB + h * 4);
            float4 a3 = *reinterpret_cast<const float4*>(x + (size_t)(t0 + 3) * EMB + h * 4);
            ull m01p0[9], m23p0[9], m01p1[9], m23p1[9];
            make_monomials(a0, a1, m01p0, m23p0);
            make_monomials(a2, a3, m01p1, m23p1);

#pragma unroll
            for (int i4 = 0; i4 < 4; ++i4) {
                const float* Tb = sT + ((h * 4 + i4) * 9) * RPAD;
                ull ev0, ev1;
#pragma unroll
                for (int a = 0; a < 9; ++a) {
                    const float* r = Tb + a * RPAD;
                    float4 ra = *reinterpret_cast<const float4*>(r);       // T0..T3
                    float4 rb = *reinterpret_cast<const float4*>(r + 4);   // T4..T7
                    float  rc = r[8];                                      // T8
                    const ull T0 = pk(ra.x, ra.x), T1 = pk(ra.y, ra.y);
                    const ull T2 = pk(ra.z, ra.z), T3 = pk(ra.w, ra.w);
                    const ull T4 = pk(rb.x, rb.x), T5 = pk(rb.y, rb.y);
                    const ull T6 = pk(rb.z, rb.z), T7 = pk(rb.w, rb.w);
                    const ull T8 = pk(rc, rc);
                    ull ta0 = f2fma(T1, m23p0[1], T0);
                    ta0 = f2fma(T2, m23p0[2], ta0);
                    ta0 = f2fma(T3, m23p0[3], ta0);
                    ta0 = f2fma(T4, m23p0[4], ta0);
                    ta0 = f2fma(T5, m23p0[5], ta0);
                    ta0 = f2fma(T6, m23p0[6], ta0);
                    ta0 = f2fma(T7, m23p0[7], ta0);
                    ta0 = f2fma(T8, m23p0[8], ta0);
                    ull ta1 = f2fma(T1, m23p1[1], T0);
                    ta1 = f2fma(T2, m23p1[2], ta1);
                    ta1 = f2fma(T3, m23p1[3], ta1);
                    ta1 = f2fma(T4, m23p1[4], ta1);
                    ta1 = f2fma(T5, m23p1[5], ta1);
                    ta1 = f2fma(T6, m23p1[6], ta1);
                    ta1 = f2fma(T7, m23p1[7], ta1);
                    ta1 = f2fma(T8, m23p1[8], ta1);
                    if (a == 0) { ev0 = ta0; ev1 = ta1; }      // m01[0] = 1
                    else {
                        ev0 = f2fma(ta0, m01p0[a], ev0);
                        ev1 = f2fma(ta1, m01p1[a], ev1);
                    }
                }
                const int f = h * 4 + i4;
                const int base = ((f >> 1) * 64) * 2 + (f & 1);
                sEv[base + (lane + 0)  * 2] = ev0;   // pairLocal = lane
                sEv[base + (lane + 32) * 2] = ev1;   // pairLocal = lane + 32
            }
        }
    }
    __syncthreads();

    // ======================== Phase B: out = W ev + b =======================
    {
        const int pl  = threadIdx.x & 31;             // quad id within block
        const int eg  = threadIdx.x >> 5;             // e-group 0..3
        const int e0  = eg * 8;
        const int tq  = (blockIdx.x * 32 + pl) * 4;   // first of 4 tokens
        const ulonglong2* evV = reinterpret_cast<const ulonglong2*>(sEv);

        ull acc[16];                                  // [ei][pair]
#pragma unroll
        for (int ei = 0; ei < 8; ++ei) {
            const float be = sb[e0 + ei];
            acc[ei * 2 + 0] = pk(be, be);
            acc[ei * 2 + 1] = pk(be, be);
        }

#pragma unroll
        for (int fq = 0; fq < 8; ++fq) {              // f = fq*4 .. fq*4+3
            ulonglong2 e0a = evV[(2 * fq)     * 64 + pl];        // pair0: f, f+1
            ulonglong2 e0b = evV[(2 * fq + 1) * 64 + pl];        // pair0: f+2, f+3
            ulonglong2 e1a = evV[(2 * fq)     * 64 + pl + 32];   // pair1
            ulonglong2 e1b = evV[(2 * fq + 1) * 64 + pl + 32];
#pragma unroll
            for (int ei = 0; ei < 8; ++ei) {
                float4 w = *reinterpret_cast<const float4*>(sW + (e0 + ei) * EMB + fq * 4);
                const ull w0 = pk(w.x, w.x), w1 = pk(w.y, w.y);
                const ull w2 = pk(w.z, w.z), w3 = pk(w.w, w.w);
                ull aA = acc[ei * 2 + 0];
                aA = f2fma(w0, e0a.x, aA);
                aA = f2fma(w1, e0a.y, aA);
                aA = f2fma(w2, e0b.x, aA);
                aA = f2fma(w3, e0b.y, aA);
                acc[ei * 2 + 0] = aA;
                ull aB = acc[ei * 2 + 1];
                aB = f2fma(w0, e1a.x, aB);
                aB = f2fma(w1, e1a.y, aB);
                aB = f2fma(w2, e1b.x, aB);
                aB = f2fma(w3, e1b.y, aB);
                acc[ei * 2 + 1] = aB;
            }
        }

        // transpose 8e x 4tok from accumulators and store 2 STG.128 per token
        float o[4][8];
#pragma unroll
        for (int ei = 0; ei < 8; ++ei) {
            upk(acc[ei * 2 + 0], o[0][ei], o[1][ei]);
            upk(acc[ei * 2 + 1], o[2][ei], o[3][ei]);
        }
#pragma unroll
        for (int tk = 0; tk < 4; ++tk) {
            float* dst = out + (size_t)(tq + tk) * EMB + e0;
            *reinterpret_cast<float4*>(dst)     = make_float4(o[tk][0], o[tk][1], o[tk][2], o[tk][3]);
            *reinterpret_cast<float4*>(dst + 4) = make_float4(o[tk][4], o[tk][5], o[tk][6], o[tk][7]);
        }
    }
}

// ============================================================================
extern "C" void kernel_launch(void* const* d_in, const int* in_sizes, int n_in,
                              void* d_out, int out_size) {
    // Identify inputs by element count (all distinct):
    // x: 4194304, params: 192, W_out: 1024, b_out: 32
    const float* x = 0; const float* params = 0; const float* W = 0; const float* b = 0;
    for (int i = 0; i < n_in; ++i) {
        switch (in_sizes[i]) {
            case 4194304: x      = (const float*)d_in[i]; break;
            case 192:     params = (const float*)d_in[i]; break;
            case 1024:    W      = (const float*)d_in[i]; break;
            case 32:      b      = (const float*)d_in[i]; break;
            default: break;
        }
    }
    float* out = (float*)d_out;

    precompute_T_kernel<<<NH, 128>>>(params);
    fused_kernel<<<1024, 128>>>(x, W, b, out);   // 1024 blocks x 128 tokens
}